// round 9
// baseline (speedup 1.0000x reference)
#include <cuda_runtime.h>
#include <cuda_fp16.h>
#include <cstdint>

#define Nn 50000
#define Ee 400000
#define F_IN 128
#define Hh 4
#define FULLMASK 0xffffffffu
#define NB 196   // ceil(Nn/256)

// ---------------- device scratch (static, no allocation) ----------------
__device__ int    g_is64;
__device__ int    g_src[Ee];
__device__ int    g_dst[Ee];
__device__ int    g_indeg[Nn];
__device__ int    g_rowstart[Nn + 1];
__device__ int    g_cursor[Nn];
__device__ int    g_csr[Ee];
__device__ int    g_blocksum[256];
__device__ int    g_blockoff[256];
// head-major: [h][n][16]
__device__ float  g_Q[Hh * Nn * 16];
__device__ float  g_K0[Hh * Nn * 16];
__device__ float  g_V[Hh * Nn * 16];
__device__ float  g_Ka[Hh * Nn * 16];
__device__ float  g_Kb[Hh * Nn * 16];
// fp16 inter-hop moment state, head-major: [h][n][256] (d*16+c inside)
__device__ __half g_Ma[(size_t)Hh * Nn * 256];
__device__ __half g_Mb[(size_t)Hh * Nn * 256];
__device__ float  g_hid[Nn * 64];        // node-major for k_out
__device__ float  g_gamma[16];           // [h][k], k=0 unused
__device__ float  g_temp0[4];

// ---------------- setup kernels ----------------
__global__ void k_zero_indeg() {
    int i = blockIdx.x * blockDim.x + threadIdx.x;
    if (i < Nn) g_indeg[i] = 0;
}

// int64 vs int32 sniff: if int64 (ids < 2^31), every odd int32 word is zero.
__global__ void k_sniff(const int* __restrict__ p) {
    int lane = threadIdx.x;
    int nz = 0;
    #pragma unroll
    for (int k = 0; k < 32; k++) {
        int i = 1 + 2 * (lane + 32 * k);
        nz += (p[i] != 0);
    }
    #pragma unroll
    for (int o = 16; o; o >>= 1) nz += __shfl_down_sync(FULLMASK, nz, o);
    if (lane == 0) g_is64 = (nz == 0) ? 1 : 0;
}

__global__ void k_edges(const void* __restrict__ ei) {
    int e = blockIdx.x * blockDim.x + threadIdx.x;
    if (e >= Ee) return;
    int s, d;
    if (g_is64) {
        const long long* p = (const long long*)ei;
        s = (int)p[e]; d = (int)p[Ee + e];
    } else {
        const int* p = (const int*)ei;
        s = p[e]; d = p[Ee + e];
    }
    g_src[e] = s;
    g_dst[e] = d;
    atomicAdd(&g_indeg[d], 1);
}

// grid scan, stage A: per-block sums
__global__ __launch_bounds__(256) void k_scanA() {
    __shared__ int sh[8];
    int i = blockIdx.x * 256 + threadIdx.x;
    int v = (i < Nn) ? g_indeg[i] : 0;
    #pragma unroll
    for (int o = 16; o; o >>= 1) v += __shfl_down_sync(FULLMASK, v, o);
    if ((threadIdx.x & 31) == 0) sh[threadIdx.x >> 5] = v;
    __syncthreads();
    if (threadIdx.x < 8) {
        int t = sh[threadIdx.x];
        #pragma unroll
        for (int o = 4; o; o >>= 1) t += __shfl_down_sync(0xffu, t, o);
        if (threadIdx.x == 0) g_blocksum[blockIdx.x] = t;
    }
}

// stage B: scan the block sums (1 block)
__global__ __launch_bounds__(256) void k_scanB() {
    __shared__ int sh[256];
    int tid = threadIdx.x;
    int v = (tid < NB) ? g_blocksum[tid] : 0;
    sh[tid] = v;
    __syncthreads();
    for (int o = 1; o < 256; o <<= 1) {
        int t = (tid >= o) ? sh[tid - o] : 0;
        __syncthreads();
        sh[tid] += t;
        __syncthreads();
    }
    if (tid < NB) g_blockoff[tid] = sh[tid] - v;
}

// stage C: local exclusive scan + block offset; write rowstart AND cursor
__global__ __launch_bounds__(256) void k_scanC() {
    __shared__ int sh[256];
    int tid = threadIdx.x;
    int i = blockIdx.x * 256 + tid;
    int v = (i < Nn) ? g_indeg[i] : 0;
    sh[tid] = v;
    __syncthreads();
    for (int o = 1; o < 256; o <<= 1) {
        int t = (tid >= o) ? sh[tid - o] : 0;
        __syncthreads();
        sh[tid] += t;
        __syncthreads();
    }
    int excl = sh[tid] - v + g_blockoff[blockIdx.x];
    if (i < Nn) { g_rowstart[i] = excl; g_cursor[i] = excl; }
    if (i == 0) g_rowstart[Nn] = Ee;
}

__global__ void k_scatter() {
    int e = blockIdx.x * blockDim.x + threadIdx.x;
    if (e >= Ee) return;
    int d = g_dst[e];
    int pos = atomicAdd(&g_cursor[d], 1);
    g_csr[pos] = g_src[e];
}

// sort each CSR row ascending -> deterministic summation order
__global__ void k_sortrows() {
    int n = blockIdx.x * blockDim.x + threadIdx.x;
    if (n >= Nn) return;
    int beg = g_rowstart[n], end = g_rowstart[n + 1];
    for (int i = beg + 1; i < end; i++) {
        int v = g_csr[i];
        int j = i - 1;
        while (j >= beg && g_csr[j] > v) { g_csr[j + 1] = g_csr[j]; j--; }
        g_csr[j + 1] = v;
    }
}

__global__ void k_gamma(const float* __restrict__ hopwise, const float* __restrict__ temp) {
    if (threadIdx.x == 0 && blockIdx.x == 0) {
        for (int k = 0; k < 4; k++) {
            float mx = -1e30f;
            for (int h = 0; h < 4; h++) mx = fmaxf(mx, temp[h * 4 + k]);
            float ex[4], ssum = 0.f;
            for (int h = 0; h < 4; h++) { ex[h] = __expf(temp[h * 4 + k] - mx); ssum += ex[h]; }
            for (int h = 0; h < 4; h++) g_gamma[h * 4 + k] = hopwise[k] * ex[h] / ssum;
        }
        for (int h = 0; h < 4; h++) g_temp0[h] = temp[h * 4 + 0];
    }
}

// ---------------- fused input transform + QKV ----------------
__global__ __launch_bounds__(256) void k_qkv(
    const float* __restrict__ x,
    const float* __restrict__ Wi, const float* __restrict__ bi,
    const float* __restrict__ Wq, const float* __restrict__ bq,
    const float* __restrict__ Wk, const float* __restrict__ bk,
    const float* __restrict__ Wv, const float* __restrict__ bv)
{
    __shared__ float hs[4][64];
    int j = threadIdx.x & 63;
    int g = threadIdx.x >> 6;          // 4 node slots per iteration
    int jh = j >> 4;                   // head of this output column
    int jd = j & 15;
    int n0 = blockIdx.x * 64;
    for (int it = 0; it < 16; ++it) {
        int n = n0 + it * 4 + g;
        float acc = __ldg(bi + j);
        if (n < Nn) {
            const float* xr = x + (size_t)n * F_IN;
            #pragma unroll 8
            for (int k2 = 0; k2 < F_IN; k2++)
                acc = fmaf(__ldg(xr + k2), __ldg(Wi + k2 * 64 + j), acc);
        }
        __syncthreads();
        hs[g][j] = fmaxf(acc, 0.f);
        __syncthreads();
        if (n < Nn) {
            float aq = __ldg(bq + j), ak = __ldg(bk + j), av = __ldg(bv + j);
            #pragma unroll
            for (int k2 = 0; k2 < 64; k2++) {
                float hv = hs[g][k2];
                aq = fmaf(hv, __ldg(Wq + k2 * 64 + j), aq);
                ak = fmaf(hv, __ldg(Wk + k2 * 64 + j), ak);
                av = fmaf(hv, __ldg(Wv + k2 * 64 + j), av);
            }
            size_t hm = (size_t)jh * Nn * 16 + n * 16 + jd;   // head-major
            g_Q[hm]  = (aq > 0.f) ? (1.f + aq) : __expf(aq);
            g_K0[hm] = (ak > 0.f) ? (1.f + ak) : __expf(ak);
            g_V[hm]  = av;
        }
    }
}

// ---------------- hop epilogue (head-major inputs, fp16 M store) ----------------
// lane = d*2 + ch; lane owns M[d][ch*8 .. ch*8+7]
__device__ __forceinline__ void hop_epilogue(
    int n, int h, int lane, int d, int ch,
    const float m[8], float kt, int hop, bool first, bool writeM,
    __half* __restrict__ Mout_h, float* __restrict__ Kout_h)
{
    float q = __ldg(g_Q + (size_t)h * Nn * 16 + n * 16 + d);
    float den = q * kt;
    #pragma unroll
    for (int msk = 2; msk <= 16; msk <<= 1) den += __shfl_xor_sync(FULLMASK, den, msk);
    den += 1e-5f;

    float hm[8];
    #pragma unroll
    for (int jj = 0; jj < 8; jj++) {
        float t = q * m[jj];
        #pragma unroll
        for (int msk = 2; msk <= 16; msk <<= 1) t += __shfl_xor_sync(FULLMASK, t, msk);
        hm[jj] = t;
    }

    if (writeM) {
        __half2 p0 = __floats2half2_rn(m[0], m[1]);
        __half2 p1 = __floats2half2_rn(m[2], m[3]);
        __half2 p2 = __floats2half2_rn(m[4], m[5]);
        __half2 p3 = __floats2half2_rn(m[6], m[7]);
        uint4 pk;
        pk.x = *(unsigned*)&p0; pk.y = *(unsigned*)&p1;
        pk.z = *(unsigned*)&p2; pk.w = *(unsigned*)&p3;
        *(uint4*)(Mout_h + (size_t)n * 256 + lane * 8) = pk;
        if (ch == 0) Kout_h[n * 16 + d] = kt;
    }

    if (d == 0) {  // lanes 0 (c=0..7) and 1 (c=8..15) write hidden
        float inv = g_gamma[h * 4 + hop] / den;
        float* hp = g_hid + n * 64 + h * 16 + ch * 8;
        if (first) {
            float t0 = g_temp0[h];
            const float* vp = g_V + (size_t)h * Nn * 16 + n * 16 + ch * 8;
            #pragma unroll
            for (int jj = 0; jj < 8; jj++) hp[jj] = vp[jj] * t0 + hm[jj] * inv;
        } else {
            #pragma unroll
            for (int jj = 0; jj < 8; jj++) hp[jj] += hm[jj] * inv;
        }
    }
}

// ---------------- hop 1: form M0 = Kt0 (x) V on the fly ----------------
// w = h*Nn + n  -> blocks execute in head order -> per-head L2 residency
__global__ __launch_bounds__(256) void k_hop1() {
    int w = (blockIdx.x * 256 + threadIdx.x) >> 5;
    int lane = threadIdx.x & 31;
    if (w >= Nn * Hh) return;
    int h = w / Nn, n = w - h * Nn;
    int d = lane >> 1, ch = lane & 1;
    const float* __restrict__ K0h = g_K0 + (size_t)h * Nn * 16;
    const float* __restrict__ Vh  = g_V  + (size_t)h * Nn * 16;

    float m[8] = {0, 0, 0, 0, 0, 0, 0, 0};
    float kt = 0.f;
    int beg = g_rowstart[n];
    int deg = g_rowstart[n + 1] - beg;
    for (int base = 0; base < deg; base += 32) {
        int idx = base + lane;
        int s_l = (idx < deg) ? g_csr[beg + idx] : 0;
        int cnt = min(32, deg - base);
        #pragma unroll 4
        for (int i = 0; i < cnt; i++) {
            int s = __shfl_sync(FULLMASK, s_l, i);
            float ks = __ldg(K0h + s * 16 + d);
            const float4* vb = (const float4*)(Vh + s * 16 + ch * 8);
            float4 va = __ldg(vb), vc = __ldg(vb + 1);
            kt += ks;
            m[0] = fmaf(ks, va.x, m[0]); m[1] = fmaf(ks, va.y, m[1]);
            m[2] = fmaf(ks, va.z, m[2]); m[3] = fmaf(ks, va.w, m[3]);
            m[4] = fmaf(ks, vc.x, m[4]); m[5] = fmaf(ks, vc.y, m[5]);
            m[6] = fmaf(ks, vc.z, m[6]); m[7] = fmaf(ks, vc.w, m[7]);
        }
    }
    hop_epilogue(n, h, lane, d, ch, m, kt, 1, true, true,
                 g_Ma + (size_t)h * Nn * 256, g_Ka + (size_t)h * Nn * 16);
}

// ---------------- hops 2,3: gather fp16 M (head-major) ----------------
__global__ __launch_bounds__(256) void k_hop23(int hop) {
    int w = (blockIdx.x * 256 + threadIdx.x) >> 5;
    int lane = threadIdx.x & 31;
    if (w >= Nn * Hh) return;
    int h = w / Nn, n = w - h * Nn;
    int d = lane >> 1, ch = lane & 1;

    const __half* __restrict__ Min_h = ((hop == 2) ? g_Ma : g_Mb) + (size_t)h * Nn * 256;
    const float*  __restrict__ Kin_h = ((hop == 2) ? g_Ka : g_Kb) + (size_t)h * Nn * 16;
    bool writeM = (hop == 2);

    float m[8] = {0, 0, 0, 0, 0, 0, 0, 0};
    float kt = 0.f;
    int beg = g_rowstart[n];
    int deg = g_rowstart[n + 1] - beg;
    int lo8 = lane * 8;
    for (int base = 0; base < deg; base += 32) {
        int idx = base + lane;
        int s_l = (idx < deg) ? g_csr[beg + idx] : 0;
        int cnt = min(32, deg - base);
        #pragma unroll 4
        for (int i = 0; i < cnt; i++) {
            int s = __shfl_sync(FULLMASK, s_l, i);
            uint4 pk = __ldg((const uint4*)(Min_h + (size_t)s * 256 + lo8));
            float2 f0 = __half22float2(*(__half2*)&pk.x);
            float2 f1 = __half22float2(*(__half2*)&pk.y);
            float2 f2 = __half22float2(*(__half2*)&pk.z);
            float2 f3 = __half22float2(*(__half2*)&pk.w);
            m[0] += f0.x; m[1] += f0.y; m[2] += f1.x; m[3] += f1.y;
            m[4] += f2.x; m[5] += f2.y; m[6] += f3.x; m[7] += f3.y;
            kt += __ldg(Kin_h + s * 16 + d);
        }
    }
    hop_epilogue(n, h, lane, d, ch, m, kt, hop, false, writeM,
                 g_Mb + (size_t)h * Nn * 256, g_Kb + (size_t)h * Nn * 16);
}

// ---------------- output projection ----------------
__global__ __launch_bounds__(256) void k_out(const float* __restrict__ Wo,
                                             const float* __restrict__ bo,
                                             float* __restrict__ out)
{
    int t = blockIdx.x * blockDim.x + threadIdx.x;
    int n = t >> 4, c = t & 15;
    if (n >= Nn) return;
    float acc = __ldg(bo + c);
    const float* hr = g_hid + n * 64;
    #pragma unroll
    for (int k = 0; k < 64; k++)
        acc = fmaf(hr[k], __ldg(Wo + k * 16 + c), acc);
    out[n * 16 + c] = acc;
}

// ---------------- launcher ----------------
extern "C" void kernel_launch(void* const* d_in, const int* in_sizes, int n_in,
                              void* d_out, int out_size)
{
    const float* x       = (const float*)d_in[0];
    const void*  ei      = d_in[1];
    const float* Wi      = (const float*)d_in[2];
    const float* bi      = (const float*)d_in[3];
    const float* Wq      = (const float*)d_in[4];
    const float* bq      = (const float*)d_in[5];
    const float* Wk      = (const float*)d_in[6];
    const float* bk      = (const float*)d_in[7];
    const float* Wv      = (const float*)d_in[8];
    const float* bv      = (const float*)d_in[9];
    const float* Wo      = (const float*)d_in[10];
    const float* bo      = (const float*)d_in[11];
    const float* hopwise = (const float*)d_in[12];
    const float* temp    = (const float*)d_in[13];
    float* out = (float*)d_out;

    k_zero_indeg<<<(Nn + 255) / 256, 256>>>();
    k_sniff<<<1, 32>>>((const int*)ei);
    k_edges<<<(Ee + 255) / 256, 256>>>(ei);
    k_scanA<<<NB, 256>>>();
    k_scanB<<<1, 256>>>();
    k_scanC<<<NB, 256>>>();
    k_scatter<<<(Ee + 255) / 256, 256>>>();
    k_sortrows<<<(Nn + 255) / 256, 256>>>();
    k_gamma<<<1, 32>>>(hopwise, temp);
    k_qkv<<<(Nn + 63) / 64, 256>>>(x, Wi, bi, Wq, bq, Wk, bk, Wv, bv);

    int hop_blocks = (Nn * Hh + 7) / 8;  // 8 warps/block, 1 warp per (head,node)
    k_hop1<<<hop_blocks, 256>>>();
    k_hop23<<<hop_blocks, 256>>>(2);
    k_hop23<<<hop_blocks, 256>>>(3);

    k_out<<<(Nn * 16 + 255) / 256, 256>>>(Wo, bo, out);
}

// round 12
// speedup vs baseline: 1.6945x; 1.6945x over previous
#include <cuda_runtime.h>
#include <cuda_fp16.h>
#include <cstdint>

#define Nn 50000
#define Ee 400000
#define F_IN 128
#define Hh 4
#define FULLMASK 0xffffffffu
#define NB 196   // ceil(Nn/256)

// ---------------- device scratch (static, no allocation) ----------------
__device__ int    g_is64;
__device__ int    g_src[Ee];
__device__ int    g_dst[Ee];
__device__ int    g_indeg[Nn];
__device__ int    g_rowstart[Nn + 1];
__device__ int    g_cursor[Nn];
__device__ int    g_csr[Ee];
__device__ int    g_blocksum[256];
__device__ int    g_blockoff[256];
// head-major: [h][n][16]
__device__ float  g_Q[Hh * Nn * 16];
__device__ float  g_K0[Hh * Nn * 16];
__device__ float  g_V[Hh * Nn * 16];
__device__ float  g_Ka[Hh * Nn * 16];
__device__ float  g_Kb[Hh * Nn * 16];
// fp16 inter-hop moment state, head-major: [h][n][256] (d*16+c inside)
__device__ __half g_Ma[(size_t)Hh * Nn * 256];
__device__ __half g_Mb[(size_t)Hh * Nn * 256];
__device__ float  g_hid[Nn * 64];        // node-major for k_out
__device__ float  g_gamma[16];           // [h][k], k=0 unused
__device__ float  g_temp0[4];

// ---------------- setup kernels ----------------
__global__ void k_zero_indeg() {
    int i = blockIdx.x * blockDim.x + threadIdx.x;
    if (i < Nn) g_indeg[i] = 0;
}

// int64 vs int32 sniff: if int64 (ids < 2^31), every odd int32 word is zero.
__global__ void k_sniff(const int* __restrict__ p) {
    int lane = threadIdx.x;
    int nz = 0;
    #pragma unroll
    for (int k = 0; k < 32; k++) {
        int i = 1 + 2 * (lane + 32 * k);
        nz += (p[i] != 0);
    }
    #pragma unroll
    for (int o = 16; o; o >>= 1) nz += __shfl_down_sync(FULLMASK, nz, o);
    if (lane == 0) g_is64 = (nz == 0) ? 1 : 0;
}

__global__ void k_edges(const void* __restrict__ ei) {
    int e = blockIdx.x * blockDim.x + threadIdx.x;
    if (e >= Ee) return;
    int s, d;
    if (g_is64) {
        const long long* p = (const long long*)ei;
        s = (int)p[e]; d = (int)p[Ee + e];
    } else {
        const int* p = (const int*)ei;
        s = p[e]; d = p[Ee + e];
    }
    g_src[e] = s;
    g_dst[e] = d;
    atomicAdd(&g_indeg[d], 1);
}

// grid scan, stage A: per-block sums
__global__ __launch_bounds__(256) void k_scanA() {
    __shared__ int sh[8];
    int i = blockIdx.x * 256 + threadIdx.x;
    int v = (i < Nn) ? g_indeg[i] : 0;
    #pragma unroll
    for (int o = 16; o; o >>= 1) v += __shfl_down_sync(FULLMASK, v, o);
    if ((threadIdx.x & 31) == 0) sh[threadIdx.x >> 5] = v;
    __syncthreads();
    if (threadIdx.x < 8) {
        int t = sh[threadIdx.x];
        #pragma unroll
        for (int o = 4; o; o >>= 1) t += __shfl_down_sync(0xffu, t, o);
        if (threadIdx.x == 0) g_blocksum[blockIdx.x] = t;
    }
}

// stage B: scan the block sums (1 block)
__global__ __launch_bounds__(256) void k_scanB() {
    __shared__ int sh[256];
    int tid = threadIdx.x;
    int v = (tid < NB) ? g_blocksum[tid] : 0;
    sh[tid] = v;
    __syncthreads();
    for (int o = 1; o < 256; o <<= 1) {
        int t = (tid >= o) ? sh[tid - o] : 0;
        __syncthreads();
        sh[tid] += t;
        __syncthreads();
    }
    if (tid < NB) g_blockoff[tid] = sh[tid] - v;
}

// stage C: local exclusive scan + block offset; write rowstart AND cursor
__global__ __launch_bounds__(256) void k_scanC() {
    __shared__ int sh[256];
    int tid = threadIdx.x;
    int i = blockIdx.x * 256 + tid;
    int v = (i < Nn) ? g_indeg[i] : 0;
    sh[tid] = v;
    __syncthreads();
    for (int o = 1; o < 256; o <<= 1) {
        int t = (tid >= o) ? sh[tid - o] : 0;
        __syncthreads();
        sh[tid] += t;
        __syncthreads();
    }
    int excl = sh[tid] - v + g_blockoff[blockIdx.x];
    if (i < Nn) { g_rowstart[i] = excl; g_cursor[i] = excl; }
    if (i == 0) g_rowstart[Nn] = Ee;
}

__global__ void k_scatter() {
    int e = blockIdx.x * blockDim.x + threadIdx.x;
    if (e >= Ee) return;
    int d = g_dst[e];
    int pos = atomicAdd(&g_cursor[d], 1);
    g_csr[pos] = g_src[e];
}

// sort each CSR row ascending -> deterministic summation order
__global__ void k_sortrows() {
    int n = blockIdx.x * blockDim.x + threadIdx.x;
    if (n >= Nn) return;
    int beg = g_rowstart[n], end = g_rowstart[n + 1];
    for (int i = beg + 1; i < end; i++) {
        int v = g_csr[i];
        int j = i - 1;
        while (j >= beg && g_csr[j] > v) { g_csr[j + 1] = g_csr[j]; j--; }
        g_csr[j + 1] = v;
    }
}

__global__ void k_gamma(const float* __restrict__ hopwise, const float* __restrict__ temp) {
    if (threadIdx.x == 0 && blockIdx.x == 0) {
        for (int k = 0; k < 4; k++) {
            float mx = -1e30f;
            for (int h = 0; h < 4; h++) mx = fmaxf(mx, temp[h * 4 + k]);
            float ex[4], ssum = 0.f;
            for (int h = 0; h < 4; h++) { ex[h] = __expf(temp[h * 4 + k] - mx); ssum += ex[h]; }
            for (int h = 0; h < 4; h++) g_gamma[h * 4 + k] = hopwise[k] * ex[h] / ssum;
        }
        for (int h = 0; h < 4; h++) g_temp0[h] = temp[h * 4 + 0];
    }
}

// ---------------- fused input transform + QKV ----------------
__global__ __launch_bounds__(256) void k_qkv(
    const float* __restrict__ x,
    const float* __restrict__ Wi, const float* __restrict__ bi,
    const float* __restrict__ Wq, const float* __restrict__ bq,
    const float* __restrict__ Wk, const float* __restrict__ bk,
    const float* __restrict__ Wv, const float* __restrict__ bv)
{
    __shared__ float hs[4][64];
    int j = threadIdx.x & 63;
    int g = threadIdx.x >> 6;          // 4 node slots per iteration
    int jh = j >> 4;                   // head of this output column
    int jd = j & 15;
    int n0 = blockIdx.x * 64;
    for (int it = 0; it < 16; ++it) {
        int n = n0 + it * 4 + g;
        float acc = __ldg(bi + j);
        if (n < Nn) {
            const float* xr = x + (size_t)n * F_IN;
            #pragma unroll 8
            for (int k2 = 0; k2 < F_IN; k2++)
                acc = fmaf(__ldg(xr + k2), __ldg(Wi + k2 * 64 + j), acc);
        }
        __syncthreads();
        hs[g][j] = fmaxf(acc, 0.f);
        __syncthreads();
        if (n < Nn) {
            float aq = __ldg(bq + j), ak = __ldg(bk + j), av = __ldg(bv + j);
            #pragma unroll
            for (int k2 = 0; k2 < 64; k2++) {
                float hv = hs[g][k2];
                aq = fmaf(hv, __ldg(Wq + k2 * 64 + j), aq);
                ak = fmaf(hv, __ldg(Wk + k2 * 64 + j), ak);
                av = fmaf(hv, __ldg(Wv + k2 * 64 + j), av);
            }
            size_t hm = (size_t)jh * Nn * 16 + n * 16 + jd;   // head-major
            g_Q[hm]  = (aq > 0.f) ? (1.f + aq) : __expf(aq);
            g_K0[hm] = (ak > 0.f) ? (1.f + ak) : __expf(ak);
            g_V[hm]  = av;
        }
    }
}

// ---------------- hop epilogue (head-major inputs, fp16 M store) ----------------
// lane = d*2 + ch; lane owns M[d][ch*8 .. ch*8+7]
// float->half->float round trips are exact when m came from half accumulation.
__device__ __forceinline__ void hop_epilogue(
    int n, int h, int lane, int d, int ch,
    const float m[8], float kt, int hop, bool first, bool writeM,
    __half* __restrict__ Mout_h, float* __restrict__ Kout_h)
{
    float q = __ldg(g_Q + (size_t)h * Nn * 16 + n * 16 + d);
    float den = q * kt;
    #pragma unroll
    for (int msk = 2; msk <= 16; msk <<= 1) den += __shfl_xor_sync(FULLMASK, den, msk);
    den += 1e-5f;

    float hm[8];
    #pragma unroll
    for (int jj = 0; jj < 8; jj++) {
        float t = q * m[jj];
        #pragma unroll
        for (int msk = 2; msk <= 16; msk <<= 1) t += __shfl_xor_sync(FULLMASK, t, msk);
        hm[jj] = t;
    }

    if (writeM) {
        __half2 p0 = __floats2half2_rn(m[0], m[1]);
        __half2 p1 = __floats2half2_rn(m[2], m[3]);
        __half2 p2 = __floats2half2_rn(m[4], m[5]);
        __half2 p3 = __floats2half2_rn(m[6], m[7]);
        uint4 pk;
        pk.x = *(unsigned*)&p0; pk.y = *(unsigned*)&p1;
        pk.z = *(unsigned*)&p2; pk.w = *(unsigned*)&p3;
        *(uint4*)(Mout_h + (size_t)n * 256 + lane * 8) = pk;
        if (ch == 0) Kout_h[n * 16 + d] = kt;
    }

    if (d == 0) {  // lanes 0 (c=0..7) and 1 (c=8..15) write hidden
        float inv = g_gamma[h * 4 + hop] / den;
        float* hp = g_hid + n * 64 + h * 16 + ch * 8;
        if (first) {
            float t0 = g_temp0[h];
            const float* vp = g_V + (size_t)h * Nn * 16 + n * 16 + ch * 8;
            #pragma unroll
            for (int jj = 0; jj < 8; jj++) hp[jj] = vp[jj] * t0 + hm[jj] * inv;
        } else {
            #pragma unroll
            for (int jj = 0; jj < 8; jj++) hp[jj] += hm[jj] * inv;
        }
    }
}

// ---------------- hop 1: form M0 = Kt0 (x) V on the fly ----------------
// w = h*Nn + n  -> blocks execute in head order -> per-head L2 residency
__global__ __launch_bounds__(256) void k_hop1() {
    int w = (blockIdx.x * 256 + threadIdx.x) >> 5;
    int lane = threadIdx.x & 31;
    if (w >= Nn * Hh) return;
    int h = w / Nn, n = w - h * Nn;
    int d = lane >> 1, ch = lane & 1;
    const float* __restrict__ K0h = g_K0 + (size_t)h * Nn * 16;
    const float* __restrict__ Vh  = g_V  + (size_t)h * Nn * 16;

    float m[8] = {0, 0, 0, 0, 0, 0, 0, 0};
    float kt = 0.f;
    int beg = g_rowstart[n];
    int deg = g_rowstart[n + 1] - beg;
    for (int base = 0; base < deg; base += 32) {
        int idx = base + lane;
        int s_l = (idx < deg) ? g_csr[beg + idx] : 0;
        int cnt = min(32, deg - base);
        #pragma unroll 4
        for (int i = 0; i < cnt; i++) {
            int s = __shfl_sync(FULLMASK, s_l, i);
            float ks = __ldg(K0h + s * 16 + d);
            const float4* vb = (const float4*)(Vh + s * 16 + ch * 8);
            float4 va = __ldg(vb), vc = __ldg(vb + 1);
            kt += ks;
            m[0] = fmaf(ks, va.x, m[0]); m[1] = fmaf(ks, va.y, m[1]);
            m[2] = fmaf(ks, va.z, m[2]); m[3] = fmaf(ks, va.w, m[3]);
            m[4] = fmaf(ks, vc.x, m[4]); m[5] = fmaf(ks, vc.y, m[5]);
            m[6] = fmaf(ks, vc.z, m[6]); m[7] = fmaf(ks, vc.w, m[7]);
        }
    }
    hop_epilogue(n, h, lane, d, ch, m, kt, 1, true, true,
                 g_Ma + (size_t)h * Nn * 256, g_Ka + (size_t)h * Nn * 16);
}

// ---------------- hops 2,3: gather fp16 M, accumulate in half2 ----------------
__global__ __launch_bounds__(256) void k_hop23(int hop) {
    int w = (blockIdx.x * 256 + threadIdx.x) >> 5;
    int lane = threadIdx.x & 31;
    if (w >= Nn * Hh) return;
    int h = w / Nn, n = w - h * Nn;
    int d = lane >> 1, ch = lane & 1;

    const __half* __restrict__ Min_h = ((hop == 2) ? g_Ma : g_Mb) + (size_t)h * Nn * 256;
    const float*  __restrict__ Kin_h = ((hop == 2) ? g_Ka : g_Kb) + (size_t)h * Nn * 16;
    bool writeM = (hop == 2);

    __half2 acc0 = __float2half2_rn(0.f);
    __half2 acc1 = acc0, acc2 = acc0, acc3 = acc0;
    float kt = 0.f;
    int beg = g_rowstart[n];
    int deg = g_rowstart[n + 1] - beg;
    int lo8 = lane * 8;
    for (int base = 0; base < deg; base += 32) {
        int idx = base + lane;
        int s_l = (idx < deg) ? g_csr[beg + idx] : 0;
        int cnt = min(32, deg - base);
        #pragma unroll 4
        for (int i = 0; i < cnt; i++) {
            int s = __shfl_sync(FULLMASK, s_l, i);
            uint4 pk = __ldg((const uint4*)(Min_h + (size_t)s * 256 + lo8));
            acc0 = __hadd2(acc0, *(__half2*)&pk.x);
            acc1 = __hadd2(acc1, *(__half2*)&pk.y);
            acc2 = __hadd2(acc2, *(__half2*)&pk.z);
            acc3 = __hadd2(acc3, *(__half2*)&pk.w);
            kt += __ldg(Kin_h + s * 16 + d);
        }
    }
    // one-time convert (8 H2F per lane total)
    float2 f0 = __half22float2(acc0), f1 = __half22float2(acc1);
    float2 f2 = __half22float2(acc2), f3 = __half22float2(acc3);
    float m[8] = {f0.x, f0.y, f1.x, f1.y, f2.x, f2.y, f3.x, f3.y};
    hop_epilogue(n, h, lane, d, ch, m, kt, hop, false, writeM,
                 g_Mb + (size_t)h * Nn * 256, g_Kb + (size_t)h * Nn * 16);
}

// ---------------- output projection ----------------
__global__ __launch_bounds__(256) void k_out(const float* __restrict__ Wo,
                                             const float* __restrict__ bo,
                                             float* __restrict__ out)
{
    int t = blockIdx.x * blockDim.x + threadIdx.x;
    int n = t >> 4, c = t & 15;
    if (n >= Nn) return;
    float acc = __ldg(bo + c);
    const float* hr = g_hid + n * 64;
    #pragma unroll
    for (int k = 0; k < 64; k++)
        acc = fmaf(hr[k], __ldg(Wo + k * 16 + c), acc);
    out[n * 16 + c] = acc;
}

// ---------------- launcher ----------------
extern "C" void kernel_launch(void* const* d_in, const int* in_sizes, int n_in,
                              void* d_out, int out_size)
{
    const float* x       = (const float*)d_in[0];
    const void*  ei      = d_in[1];
    const float* Wi      = (const float*)d_in[2];
    const float* bi      = (const float*)d_in[3];
    const float* Wq      = (const float*)d_in[4];
    const float* bq      = (const float*)d_in[5];
    const float* Wk      = (const float*)d_in[6];
    const float* bk      = (const float*)d_in[7];
    const float* Wv      = (const float*)d_in[8];
    const float* bv      = (const float*)d_in[9];
    const float* Wo      = (const float*)d_in[10];
    const float* bo      = (const float*)d_in[11];
    const float* hopwise = (const float*)d_in[12];
    const float* temp    = (const float*)d_in[13];
    float* out = (float*)d_out;

    k_zero_indeg<<<(Nn + 255) / 256, 256>>>();
    k_sniff<<<1, 32>>>((const int*)ei);
    k_edges<<<(Ee + 255) / 256, 256>>>(ei);
    k_scanA<<<NB, 256>>>();
    k_scanB<<<1, 256>>>();
    k_scanC<<<NB, 256>>>();
    k_scatter<<<(Ee + 255) / 256, 256>>>();
    k_sortrows<<<(Nn + 255) / 256, 256>>>();
    k_gamma<<<1, 32>>>(hopwise, temp);
    k_qkv<<<(Nn + 63) / 64, 256>>>(x, Wi, bi, Wq, bq, Wk, bk, Wv, bv);

    int hop_blocks = (Nn * Hh + 7) / 8;  // 8 warps/block, 1 warp per (head,node)
    k_hop1<<<hop_blocks, 256>>>();
    k_hop23<<<hop_blocks, 256>>>(2);
    k_hop23<<<hop_blocks, 256>>>(3);

    k_out<<<(Nn * 16 + 255) / 256, 256>>>(Wo, bo, out);
}

// round 14
// speedup vs baseline: 1.8493x; 1.0914x over previous
#include <cuda_runtime.h>
#include <cuda_fp16.h>
#include <cstdint>

#define Nn 50000
#define Ee 400000
#define F_IN 128
#define Hh 4
#define FULLMASK 0xffffffffu
#define NB 196   // ceil(Nn/256)

// ---------------- device scratch (static, no allocation) ----------------
__device__ int    g_is64;
__device__ int    g_src[Ee];
__device__ int    g_dst[Ee];
__device__ int    g_indeg[Nn];
__device__ int    g_rowstart[Nn + 1];
__device__ int    g_cursor[Nn];
__device__ int    g_csr[Ee];
__device__ int    g_blocksum[256];
__device__ int    g_blockoff[256];
// head-major: [h][n][16]
__device__ float  g_Q[Hh * Nn * 16];
__device__ float  g_K0[Hh * Nn * 16];
__device__ float  g_V[Hh * Nn * 16];
__device__ float  g_Ka[Hh * Nn * 16];
__device__ float  g_Kb[Hh * Nn * 16];
// fp16 inter-hop moment state, head-major: [h][n][256] (d*16+c inside)
__device__ __half g_Ma[(size_t)Hh * Nn * 256];
__device__ __half g_Mb[(size_t)Hh * Nn * 256];
__device__ float  g_hid[Nn * 64];        // node-major for k_out
__device__ float  g_gamma[16];           // [h][k], k=0 unused
__device__ float  g_temp0[4];

// ---------------- setup kernels ----------------
__global__ void k_zero_indeg() {
    int i = blockIdx.x * blockDim.x + threadIdx.x;
    if (i < Nn) g_indeg[i] = 0;
}

// int64 vs int32 sniff: if int64 (ids < 2^31), every odd int32 word is zero.
__global__ void k_sniff(const int* __restrict__ p) {
    int lane = threadIdx.x;
    int nz = 0;
    #pragma unroll
    for (int k = 0; k < 32; k++) {
        int i = 1 + 2 * (lane + 32 * k);
        nz += (p[i] != 0);
    }
    #pragma unroll
    for (int o = 16; o; o >>= 1) nz += __shfl_down_sync(FULLMASK, nz, o);
    if (lane == 0) g_is64 = (nz == 0) ? 1 : 0;
}

__global__ void k_edges(const void* __restrict__ ei) {
    int e = blockIdx.x * blockDim.x + threadIdx.x;
    if (e >= Ee) return;
    int s, d;
    if (g_is64) {
        const long long* p = (const long long*)ei;
        s = (int)p[e]; d = (int)p[Ee + e];
    } else {
        const int* p = (const int*)ei;
        s = p[e]; d = p[Ee + e];
    }
    g_src[e] = s;
    g_dst[e] = d;
    atomicAdd(&g_indeg[d], 1);
}

// grid scan, stage A: per-block sums
__global__ __launch_bounds__(256) void k_scanA() {
    __shared__ int sh[8];
    int i = blockIdx.x * 256 + threadIdx.x;
    int v = (i < Nn) ? g_indeg[i] : 0;
    #pragma unroll
    for (int o = 16; o; o >>= 1) v += __shfl_down_sync(FULLMASK, v, o);
    if ((threadIdx.x & 31) == 0) sh[threadIdx.x >> 5] = v;
    __syncthreads();
    if (threadIdx.x < 8) {
        int t = sh[threadIdx.x];
        #pragma unroll
        for (int o = 4; o; o >>= 1) t += __shfl_down_sync(0xffu, t, o);
        if (threadIdx.x == 0) g_blocksum[blockIdx.x] = t;
    }
}

// stage B: scan the block sums (1 block)
__global__ __launch_bounds__(256) void k_scanB() {
    __shared__ int sh[256];
    int tid = threadIdx.x;
    int v = (tid < NB) ? g_blocksum[tid] : 0;
    sh[tid] = v;
    __syncthreads();
    for (int o = 1; o < 256; o <<= 1) {
        int t = (tid >= o) ? sh[tid - o] : 0;
        __syncthreads();
        sh[tid] += t;
        __syncthreads();
    }
    if (tid < NB) g_blockoff[tid] = sh[tid] - v;
}

// stage C: local exclusive scan + block offset; write rowstart AND cursor
__global__ __launch_bounds__(256) void k_scanC() {
    __shared__ int sh[256];
    int tid = threadIdx.x;
    int i = blockIdx.x * 256 + tid;
    int v = (i < Nn) ? g_indeg[i] : 0;
    sh[tid] = v;
    __syncthreads();
    for (int o = 1; o < 256; o <<= 1) {
        int t = (tid >= o) ? sh[tid - o] : 0;
        __syncthreads();
        sh[tid] += t;
        __syncthreads();
    }
    int excl = sh[tid] - v + g_blockoff[blockIdx.x];
    if (i < Nn) { g_rowstart[i] = excl; g_cursor[i] = excl; }
    if (i == 0) g_rowstart[Nn] = Ee;
}

__global__ void k_scatter() {
    int e = blockIdx.x * blockDim.x + threadIdx.x;
    if (e >= Ee) return;
    int d = g_dst[e];
    int pos = atomicAdd(&g_cursor[d], 1);
    g_csr[pos] = g_src[e];
}

// sort each CSR row ascending (deterministic order): warp bitonic for deg<=32
__global__ __launch_bounds__(256) void k_sortrows() {
    int w = (blockIdx.x * 256 + threadIdx.x) >> 5;
    int lane = threadIdx.x & 31;
    if (w >= Nn) return;
    int beg = g_rowstart[w];
    int deg = g_rowstart[w + 1] - beg;
    if (deg <= 1) return;
    if (deg <= 32) {
        int v = (lane < deg) ? g_csr[beg + lane] : 0x7fffffff;
        #pragma unroll
        for (int k = 2; k <= 32; k <<= 1) {
            #pragma unroll
            for (int j = k >> 1; j > 0; j >>= 1) {
                int o = __shfl_xor_sync(FULLMASK, v, j);
                bool lo  = (lane & j) == 0;
                bool asc = (lane & k) == 0;
                v = (lo == asc) ? min(v, o) : max(v, o);
            }
        }
        if (lane < deg) g_csr[beg + lane] = v;
    } else if (lane == 0) {   // rare fallback
        for (int i = beg + 1; i < beg + deg; i++) {
            int v = g_csr[i];
            int j = i - 1;
            while (j >= beg && g_csr[j] > v) { g_csr[j + 1] = g_csr[j]; j--; }
            g_csr[j + 1] = v;
        }
    }
}

__global__ void k_gamma(const float* __restrict__ hopwise, const float* __restrict__ temp) {
    if (threadIdx.x == 0 && blockIdx.x == 0) {
        for (int k = 0; k < 4; k++) {
            float mx = -1e30f;
            for (int h = 0; h < 4; h++) mx = fmaxf(mx, temp[h * 4 + k]);
            float ex[4], ssum = 0.f;
            for (int h = 0; h < 4; h++) { ex[h] = __expf(temp[h * 4 + k] - mx); ssum += ex[h]; }
            for (int h = 0; h < 4; h++) g_gamma[h * 4 + k] = hopwise[k] * ex[h] / ssum;
        }
        for (int h = 0; h < 4; h++) g_temp0[h] = temp[h * 4 + 0];
    }
}

// ---------------- fused input transform + QKV (smem weights) ----------------
// smem layout (floats): sWi[128*64] | sW3[64*192] | sb[256] | sx[16*132] | sh[16*68]
#define SX_STRIDE 132
#define SH_STRIDE 68
#define QKV_SMEM_FLOATS (8192 + 12288 + 256 + 16 * SX_STRIDE + 16 * SH_STRIDE)

__global__ __launch_bounds__(256) void k_qkv(
    const float* __restrict__ x,
    const float* __restrict__ Wi, const float* __restrict__ bi,
    const float* __restrict__ Wq, const float* __restrict__ bq,
    const float* __restrict__ Wk, const float* __restrict__ bk,
    const float* __restrict__ Wv, const float* __restrict__ bv)
{
    extern __shared__ float smem[];
    float* sWi = smem;                    // [k2][64]
    float* sW3 = sWi + 8192;              // [k2][192]: q(0..63) k(64..127) v(128..191)
    float* sb  = sW3 + 12288;             // bi | bq | bk | bv
    float* sx  = sb + 256;                // [16][SX_STRIDE]
    float* sh  = sx + 16 * SX_STRIDE;     // [16][SH_STRIDE]
    int tid = threadIdx.x;

    for (int i = tid; i < 8192; i += 256) sWi[i] = __ldg(Wi + i);
    for (int i = tid; i < 4096; i += 256) {
        int k2 = i >> 6, j = i & 63;
        sW3[k2 * 192 + j]        = __ldg(Wq + i);
        sW3[k2 * 192 + 64 + j]   = __ldg(Wk + i);
        sW3[k2 * 192 + 128 + j]  = __ldg(Wv + i);
    }
    if (tid < 64) {
        sb[tid]       = __ldg(bi + tid);
        sb[64 + tid]  = __ldg(bq + tid);
        sb[128 + tid] = __ldg(bk + tid);
        sb[192 + tid] = __ldg(bv + tid);
    }
    __syncthreads();

    int n0 = blockIdx.x * 256;
    int g  = tid >> 4;        // node slot 0..15
    int jt = tid & 15;        // 4-col group: cols 4jt..4jt+3

    for (int pass = 0; pass < 16; pass++) {
        int nb = n0 + pass * 16;
        // stage x: 16 rows x 128 floats
        {
            int r = tid >> 4;
            int cc = (tid & 15) * 8;
            int n = nb + r;
            float4 a = {0, 0, 0, 0}, b = {0, 0, 0, 0};
            if (n < Nn) {
                const float4* xp = (const float4*)(x + (size_t)n * F_IN + cc);
                a = __ldg(xp); b = __ldg(xp + 1);
            }
            *(float4*)(sx + r * SX_STRIDE + cc)     = a;
            *(float4*)(sx + r * SX_STRIDE + cc + 4) = b;
        }
        __syncthreads();
        // phase 1: h = relu(x@Wi + bi), 4 cols per thread
        {
            float4 acc = *(float4*)(sb + 4 * jt);
            const float* xr = sx + g * SX_STRIDE;
            #pragma unroll 8
            for (int k2 = 0; k2 < F_IN; k2++) {
                float xv = xr[k2];
                float4 w = *(float4*)(sWi + k2 * 64 + 4 * jt);
                acc.x = fmaf(xv, w.x, acc.x);
                acc.y = fmaf(xv, w.y, acc.y);
                acc.z = fmaf(xv, w.z, acc.z);
                acc.w = fmaf(xv, w.w, acc.w);
            }
            acc.x = fmaxf(acc.x, 0.f); acc.y = fmaxf(acc.y, 0.f);
            acc.z = fmaxf(acc.z, 0.f); acc.w = fmaxf(acc.w, 0.f);
            *(float4*)(sh + g * SH_STRIDE + 4 * jt) = acc;
        }
        __syncthreads();
        // phase 2: Q/K/V = h@{Wq,Wk,Wv}+b, 12 outputs per thread
        {
            float4 aq = *(float4*)(sb + 64 + 4 * jt);
            float4 ak = *(float4*)(sb + 128 + 4 * jt);
            float4 av = *(float4*)(sb + 192 + 4 * jt);
            const float* hr = sh + g * SH_STRIDE;
            #pragma unroll 4
            for (int k2 = 0; k2 < 64; k2++) {
                float hv = hr[k2];
                const float* wr = sW3 + k2 * 192;
                float4 wq = *(float4*)(wr + 4 * jt);
                float4 wk = *(float4*)(wr + 64 + 4 * jt);
                float4 wv = *(float4*)(wr + 128 + 4 * jt);
                aq.x = fmaf(hv, wq.x, aq.x); aq.y = fmaf(hv, wq.y, aq.y);
                aq.z = fmaf(hv, wq.z, aq.z); aq.w = fmaf(hv, wq.w, aq.w);
                ak.x = fmaf(hv, wk.x, ak.x); ak.y = fmaf(hv, wk.y, ak.y);
                ak.z = fmaf(hv, wk.z, ak.z); ak.w = fmaf(hv, wk.w, ak.w);
                av.x = fmaf(hv, wv.x, av.x); av.y = fmaf(hv, wv.y, av.y);
                av.z = fmaf(hv, wv.z, av.z); av.w = fmaf(hv, wv.w, av.w);
            }
            int n = nb + g;
            if (n < Nn) {
                int c = 4 * jt;
                int hidx = c >> 4, d = c & 15;
                size_t base = (size_t)hidx * Nn * 16 + (size_t)n * 16 + d;
                float4 qo, ko;
                qo.x = (aq.x > 0.f) ? (1.f + aq.x) : __expf(aq.x);
                qo.y = (aq.y > 0.f) ? (1.f + aq.y) : __expf(aq.y);
                qo.z = (aq.z > 0.f) ? (1.f + aq.z) : __expf(aq.z);
                qo.w = (aq.w > 0.f) ? (1.f + aq.w) : __expf(aq.w);
                ko.x = (ak.x > 0.f) ? (1.f + ak.x) : __expf(ak.x);
                ko.y = (ak.y > 0.f) ? (1.f + ak.y) : __expf(ak.y);
                ko.z = (ak.z > 0.f) ? (1.f + ak.z) : __expf(ak.z);
                ko.w = (ak.w > 0.f) ? (1.f + ak.w) : __expf(ak.w);
                *(float4*)(g_Q + base)  = qo;
                *(float4*)(g_K0 + base) = ko;
                *(float4*)(g_V + base)  = av;
            }
        }
        __syncthreads();
    }
}

// ---------------- hop epilogue (head-major inputs, fp16 M store) ----------------
__device__ __forceinline__ void hop_epilogue(
    int n, int h, int lane, int d, int ch,
    const float m[8], float kt, int hop, bool first, bool writeM,
    __half* __restrict__ Mout_h, float* __restrict__ Kout_h)
{
    float q = __ldg(g_Q + (size_t)h * Nn * 16 + n * 16 + d);
    float den = q * kt;
    #pragma unroll
    for (int msk = 2; msk <= 16; msk <<= 1) den += __shfl_xor_sync(FULLMASK, den, msk);
    den += 1e-5f;

    float hm[8];
    #pragma unroll
    for (int jj = 0; jj < 8; jj++) {
        float t = q * m[jj];
        #pragma unroll
        for (int msk = 2; msk <= 16; msk <<= 1) t += __shfl_xor_sync(FULLMASK, t, msk);
        hm[jj] = t;
    }

    if (writeM) {
        __half2 p0 = __floats2half2_rn(m[0], m[1]);
        __half2 p1 = __floats2half2_rn(m[2], m[3]);
        __half2 p2 = __floats2half2_rn(m[4], m[5]);
        __half2 p3 = __floats2half2_rn(m[6], m[7]);
        uint4 pk;
        pk.x = *(unsigned*)&p0; pk.y = *(unsigned*)&p1;
        pk.z = *(unsigned*)&p2; pk.w = *(unsigned*)&p3;
        *(uint4*)(Mout_h + (size_t)n * 256 + lane * 8) = pk;
        if (ch == 0) Kout_h[n * 16 + d] = kt;
    }

    if (d == 0) {
        float inv = g_gamma[h * 4 + hop] / den;
        float* hp = g_hid + n * 64 + h * 16 + ch * 8;
        if (first) {
            float t0 = g_temp0[h];
            const float* vp = g_V + (size_t)h * Nn * 16 + n * 16 + ch * 8;
            #pragma unroll
            for (int jj = 0; jj < 8; jj++) hp[jj] = vp[jj] * t0 + hm[jj] * inv;
        } else {
            #pragma unroll
            for (int jj = 0; jj < 8; jj++) hp[jj] += hm[jj] * inv;
        }
    }
}

// ---------------- hop 1: form M0 = Kt0 (x) V on the fly ----------------
__global__ __launch_bounds__(256) void k_hop1() {
    int w = (blockIdx.x * 256 + threadIdx.x) >> 5;
    int lane = threadIdx.x & 31;
    if (w >= Nn * Hh) return;
    int h = w / Nn, n = w - h * Nn;
    int d = lane >> 1, ch = lane & 1;
    const float* __restrict__ K0h = g_K0 + (size_t)h * Nn * 16;
    const float* __restrict__ Vh  = g_V  + (size_t)h * Nn * 16;

    float m[8] = {0, 0, 0, 0, 0, 0, 0, 0};
    float kt = 0.f;
    int beg = g_rowstart[n];
    int deg = g_rowstart[n + 1] - beg;
    for (int base = 0; base < deg; base += 32) {
        int idx = base + lane;
        int s_l = (idx < deg) ? g_csr[beg + idx] : 0;
        int cnt = min(32, deg - base);
        #pragma unroll 4
        for (int i = 0; i < cnt; i++) {
            int s = __shfl_sync(FULLMASK, s_l, i);
            float ks = __ldg(K0h + s * 16 + d);
            const float4* vb = (const float4*)(Vh + s * 16 + ch * 8);
            float4 va = __ldg(vb), vc = __ldg(vb + 1);
            kt += ks;
            m[0] = fmaf(ks, va.x, m[0]); m[1] = fmaf(ks, va.y, m[1]);
            m[2] = fmaf(ks, va.z, m[2]); m[3] = fmaf(ks, va.w, m[3]);
            m[4] = fmaf(ks, vc.x, m[4]); m[5] = fmaf(ks, vc.y, m[5]);
            m[6] = fmaf(ks, vc.z, m[6]); m[7] = fmaf(ks, vc.w, m[7]);
        }
    }
    hop_epilogue(n, h, lane, d, ch, m, kt, 1, true, true,
                 g_Ma + (size_t)h * Nn * 256, g_Ka + (size_t)h * Nn * 16);
}

// ---------------- hops 2,3: gather fp16 M, accumulate in half2 ----------------
__global__ __launch_bounds__(256) void k_hop23(int hop) {
    int w = (blockIdx.x * 256 + threadIdx.x) >> 5;
    int lane = threadIdx.x & 31;
    if (w >= Nn * Hh) return;
    int h = w / Nn, n = w - h * Nn;
    int d = lane >> 1, ch = lane & 1;

    const __half* __restrict__ Min_h = ((hop == 2) ? g_Ma : g_Mb) + (size_t)h * Nn * 256;
    const float*  __restrict__ Kin_h = ((hop == 2) ? g_Ka : g_Kb) + (size_t)h * Nn * 16;
    bool writeM = (hop == 2);

    __half2 acc0 = __float2half2_rn(0.f);
    __half2 acc1 = acc0, acc2 = acc0, acc3 = acc0;
    float kt = 0.f;
    int beg = g_rowstart[n];
    int deg = g_rowstart[n + 1] - beg;
    int lo8 = lane * 8;
    for (int base = 0; base < deg; base += 32) {
        int idx = base + lane;
        int s_l = (idx < deg) ? g_csr[beg + idx] : 0;
        int cnt = min(32, deg - base);
        #pragma unroll 4
        for (int i = 0; i < cnt; i++) {
            int s = __shfl_sync(FULLMASK, s_l, i);
            uint4 pk = __ldg((const uint4*)(Min_h + (size_t)s * 256 + lo8));
            acc0 = __hadd2(acc0, *(__half2*)&pk.x);
            acc1 = __hadd2(acc1, *(__half2*)&pk.y);
            acc2 = __hadd2(acc2, *(__half2*)&pk.z);
            acc3 = __hadd2(acc3, *(__half2*)&pk.w);
            kt += __ldg(Kin_h + s * 16 + d);
        }
    }
    float2 f0 = __half22float2(acc0), f1 = __half22float2(acc1);
    float2 f2 = __half22float2(acc2), f3 = __half22float2(acc3);
    float m[8] = {f0.x, f0.y, f1.x, f1.y, f2.x, f2.y, f3.x, f3.y};
    hop_epilogue(n, h, lane, d, ch, m, kt, hop, false, writeM,
                 g_Mb + (size_t)h * Nn * 256, g_Kb + (size_t)h * Nn * 16);
}

// ---------------- output projection ----------------
__global__ __launch_bounds__(256) void k_out(const float* __restrict__ Wo,
                                             const float* __restrict__ bo,
                                             float* __restrict__ out)
{
    int t = blockIdx.x * blockDim.x + threadIdx.x;
    int n = t >> 4, c = t & 15;
    if (n >= Nn) return;
    float acc = __ldg(bo + c);
    const float* hr = g_hid + n * 64;
    #pragma unroll
    for (int k = 0; k < 64; k++)
        acc = fmaf(hr[k], __ldg(Wo + k * 16 + c), acc);
    out[n * 16 + c] = acc;
}

// ---------------- launcher ----------------
extern "C" void kernel_launch(void* const* d_in, const int* in_sizes, int n_in,
                              void* d_out, int out_size)
{
    const float* x       = (const float*)d_in[0];
    const void*  ei      = d_in[1];
    const float* Wi      = (const float*)d_in[2];
    const float* bi      = (const float*)d_in[3];
    const float* Wq      = (const float*)d_in[4];
    const float* bq      = (const float*)d_in[5];
    const float* Wk      = (const float*)d_in[6];
    const float* bk      = (const float*)d_in[7];
    const float* Wv      = (const float*)d_in[8];
    const float* bv      = (const float*)d_in[9];
    const float* Wo      = (const float*)d_in[10];
    const float* bo      = (const float*)d_in[11];
    const float* hopwise = (const float*)d_in[12];
    const float* temp    = (const float*)d_in[13];
    float* out = (float*)d_out;

    const int qkv_smem = QKV_SMEM_FLOATS * 4;   // ~95.7 KB
    cudaFuncSetAttribute(k_qkv, cudaFuncAttributeMaxDynamicSharedMemorySize, qkv_smem);

    k_zero_indeg<<<(Nn + 255) / 256, 256>>>();
    k_sniff<<<1, 32>>>((const int*)ei);
    k_edges<<<(Ee + 255) / 256, 256>>>(ei);
    k_scanA<<<NB, 256>>>();
    k_scanB<<<1, 256>>>();
    k_scanC<<<NB, 256>>>();
    k_scatter<<<(Ee + 255) / 256, 256>>>();
    k_sortrows<<<(Nn * 32 + 255) / 256, 256>>>();
    k_gamma<<<1, 32>>>(hopwise, temp);
    k_qkv<<<NB, 256, qkv_smem>>>(x, Wi, bi, Wq, bq, Wk, bk, Wv, bv);

    int hop_blocks = (Nn * Hh + 7) / 8;  // 8 warps/block, 1 warp per (head,node)
    k_hop1<<<hop_blocks, 256>>>();
    k_hop23<<<hop_blocks, 256>>>(2);
    k_hop23<<<hop_blocks, 256>>>(3);

    k_out<<<(Nn * 16 + 255) / 256, 256>>>(Wo, bo, out);
}

// round 17
// speedup vs baseline: 1.8553x; 1.0032x over previous
#include <cuda_runtime.h>
#include <cuda_fp16.h>
#include <cstdint>

#define Nn 50000
#define Ee 400000
#define F_IN 128
#define Hh 4
#define FULLMASK 0xffffffffu
#define NB 196   // ceil(Nn/256)

// ---------------- device scratch (static, no allocation) ----------------
__device__ int    g_is64;
__device__ int    g_src[Ee];
__device__ int    g_dst[Ee];
__device__ int    g_indeg[Nn];
__device__ int    g_rowstart[Nn + 1];
__device__ int    g_cursor[Nn];
__device__ int    g_csr[Ee];
__device__ int    g_blocksum[256];
// head-major: [h][n][16]
__device__ float  g_Q[Hh * Nn * 16];
__device__ float  g_K0[Hh * Nn * 16];
__device__ float  g_V[Hh * Nn * 16];
__device__ float  g_Ka[Hh * Nn * 16];
__device__ float  g_Kb[Hh * Nn * 16];
// fp16 inter-hop moment state, head-major: [h][n][256] (d*16+c inside)
__device__ __half g_Ma[(size_t)Hh * Nn * 256];
__device__ __half g_Mb[(size_t)Hh * Nn * 256];
__device__ float  g_hid[Nn * 64];        // node-major for k_out
__device__ float  g_gamma[16];           // [h][k], k=0 unused
__device__ float  g_temp0[4];

// ---------------- setup kernels ----------------
// fused: blocks 0..NB-1 zero indeg; block NB sniffs edge dtype.
// int64 (ids < 2^31) -> every odd int32 word is zero.
__global__ void k_init(const int* __restrict__ p) {
    if (blockIdx.x < NB) {
        int i = blockIdx.x * 256 + threadIdx.x;
        if (i < Nn) g_indeg[i] = 0;
    } else if (threadIdx.x < 32) {
        int lane = threadIdx.x;
        int nz = 0;
        #pragma unroll
        for (int k = 0; k < 32; k++) {
            int i = 1 + 2 * (lane + 32 * k);
            nz += (p[i] != 0);
        }
        #pragma unroll
        for (int o = 16; o; o >>= 1) nz += __shfl_down_sync(FULLMASK, nz, o);
        if (lane == 0) g_is64 = (nz == 0) ? 1 : 0;
    }
}

__global__ void k_edges(const void* __restrict__ ei) {
    int e = blockIdx.x * blockDim.x + threadIdx.x;
    if (e >= Ee) return;
    int s, d;
    if (g_is64) {
        const long long* p = (const long long*)ei;
        s = (int)p[e]; d = (int)p[Ee + e];
    } else {
        const int* p = (const int*)ei;
        s = p[e]; d = p[Ee + e];
    }
    g_src[e] = s;
    g_dst[e] = d;
    atomicAdd(&g_indeg[d], 1);
}

// grid scan, stage A: per-block sums
__global__ __launch_bounds__(256) void k_scanA() {
    __shared__ int sh[8];
    int i = blockIdx.x * 256 + threadIdx.x;
    int v = (i < Nn) ? g_indeg[i] : 0;
    #pragma unroll
    for (int o = 16; o; o >>= 1) v += __shfl_down_sync(FULLMASK, v, o);
    if ((threadIdx.x & 31) == 0) sh[threadIdx.x >> 5] = v;
    __syncthreads();
    if (threadIdx.x < 8) {
        int t = sh[threadIdx.x];
        #pragma unroll
        for (int o = 4; o; o >>= 1) t += __shfl_down_sync(0xffu, t, o);
        if (threadIdx.x == 0) g_blocksum[blockIdx.x] = t;
    }
}

// stage C (fused with B): each block computes its own offset from g_blocksum,
// then local exclusive scan; writes rowstart AND cursor.
__global__ __launch_bounds__(256) void k_scanC() {
    __shared__ int sh[256];
    int tid = threadIdx.x;
    int bid = blockIdx.x;
    // block offset = sum of blocksum[0..bid)
    int part = (tid < bid) ? g_blocksum[tid] : 0;   // bid <= 195 < 256
    sh[tid] = part;
    __syncthreads();
    #pragma unroll
    for (int o = 128; o; o >>= 1) {
        if (tid < o) sh[tid] += sh[tid + o];
        __syncthreads();
    }
    int blockoff = sh[0];
    __syncthreads();
    int i = bid * 256 + tid;
    int v = (i < Nn) ? g_indeg[i] : 0;
    sh[tid] = v;
    __syncthreads();
    for (int o = 1; o < 256; o <<= 1) {
        int t = (tid >= o) ? sh[tid - o] : 0;
        __syncthreads();
        sh[tid] += t;
        __syncthreads();
    }
    int excl = sh[tid] - v + blockoff;
    if (i < Nn) { g_rowstart[i] = excl; g_cursor[i] = excl; }
    if (i == 0) g_rowstart[Nn] = Ee;
}

__global__ void k_scatter() {
    int e = blockIdx.x * blockDim.x + threadIdx.x;
    if (e >= Ee) return;
    int d = g_dst[e];
    int pos = atomicAdd(&g_cursor[d], 1);
    g_csr[pos] = g_src[e];
}

// sort each CSR row ascending (deterministic order): warp bitonic for deg<=32
__global__ __launch_bounds__(256) void k_sortrows() {
    int w = (blockIdx.x * 256 + threadIdx.x) >> 5;
    int lane = threadIdx.x & 31;
    if (w >= Nn) return;
    int beg = g_rowstart[w];
    int deg = g_rowstart[w + 1] - beg;
    if (deg <= 1) return;
    if (deg <= 32) {
        int v = (lane < deg) ? g_csr[beg + lane] : 0x7fffffff;
        #pragma unroll
        for (int k = 2; k <= 32; k <<= 1) {
            #pragma unroll
            for (int j = k >> 1; j > 0; j >>= 1) {
                int o = __shfl_xor_sync(FULLMASK, v, j);
                bool lo  = (lane & j) == 0;
                bool asc = (lane & k) == 0;
                v = (lo == asc) ? min(v, o) : max(v, o);
            }
        }
        if (lane < deg) g_csr[beg + lane] = v;
    } else if (lane == 0) {   // rare fallback
        for (int i = beg + 1; i < beg + deg; i++) {
            int v = g_csr[i];
            int j = i - 1;
            while (j >= beg && g_csr[j] > v) { g_csr[j + 1] = g_csr[j]; j--; }
            g_csr[j + 1] = v;
        }
    }
}

__global__ void k_gamma(const float* __restrict__ hopwise, const float* __restrict__ temp) {
    if (threadIdx.x == 0 && blockIdx.x == 0) {
        for (int k = 0; k < 4; k++) {
            float mx = -1e30f;
            for (int h = 0; h < 4; h++) mx = fmaxf(mx, temp[h * 4 + k]);
            float ex[4], ssum = 0.f;
            for (int h = 0; h < 4; h++) { ex[h] = __expf(temp[h * 4 + k] - mx); ssum += ex[h]; }
            for (int h = 0; h < 4; h++) g_gamma[h * 4 + k] = hopwise[k] * ex[h] / ssum;
        }
        for (int h = 0; h < 4; h++) g_temp0[h] = temp[h * 4 + 0];
    }
}

// ---------------- fused input transform + QKV (R14 container-proven version) ----------------
// smem layout (floats): sWi[128*64] | sW3[64*192] | sb[256] | sx[16*132] | sh[16*68]
#define SX_STRIDE 132
#define SH_STRIDE 68
#define QKV_SMEM_FLOATS (8192 + 12288 + 256 + 16 * SX_STRIDE + 16 * SH_STRIDE)

__global__ __launch_bounds__(256) void k_qkv(
    const float* __restrict__ x,
    const float* __restrict__ Wi, const float* __restrict__ bi,
    const float* __restrict__ Wq, const float* __restrict__ bq,
    const float* __restrict__ Wk, const float* __restrict__ bk,
    const float* __restrict__ Wv, const float* __restrict__ bv)
{
    extern __shared__ float smem[];
    float* sWi = smem;                    // [k2][64]
    float* sW3 = sWi + 8192;              // [k2][192]: q(0..63) k(64..127) v(128..191)
    float* sb  = sW3 + 12288;             // bi | bq | bk | bv
    float* sx  = sb + 256;                // [16][SX_STRIDE]
    float* sh  = sx + 16 * SX_STRIDE;     // [16][SH_STRIDE]
    int tid = threadIdx.x;

    for (int i = tid; i < 8192; i += 256) sWi[i] = __ldg(Wi + i);
    for (int i = tid; i < 4096; i += 256) {
        int k2 = i >> 6, j = i & 63;
        sW3[k2 * 192 + j]        = __ldg(Wq + i);
        sW3[k2 * 192 + 64 + j]   = __ldg(Wk + i);
        sW3[k2 * 192 + 128 + j]  = __ldg(Wv + i);
    }
    if (tid < 64) {
        sb[tid]       = __ldg(bi + tid);
        sb[64 + tid]  = __ldg(bq + tid);
        sb[128 + tid] = __ldg(bk + tid);
        sb[192 + tid] = __ldg(bv + tid);
    }
    __syncthreads();

    int n0 = blockIdx.x * 256;
    int g  = tid >> 4;        // node slot 0..15
    int jt = tid & 15;        // 4-col group: cols 4jt..4jt+3

    for (int pass = 0; pass < 16; pass++) {
        int nb = n0 + pass * 16;
        // stage x: 16 rows x 128 floats
        {
            int r = tid >> 4;
            int cc = (tid & 15) * 8;
            int n = nb + r;
            float4 a = {0, 0, 0, 0}, b = {0, 0, 0, 0};
            if (n < Nn) {
                const float4* xp = (const float4*)(x + (size_t)n * F_IN + cc);
                a = __ldg(xp); b = __ldg(xp + 1);
            }
            *(float4*)(sx + r * SX_STRIDE + cc)     = a;
            *(float4*)(sx + r * SX_STRIDE + cc + 4) = b;
        }
        __syncthreads();
        // phase 1: h = relu(x@Wi + bi), 4 cols per thread
        {
            float4 acc = *(float4*)(sb + 4 * jt);
            const float* xr = sx + g * SX_STRIDE;
            #pragma unroll 8
            for (int k2 = 0; k2 < F_IN; k2++) {
                float xv = xr[k2];
                float4 w = *(float4*)(sWi + k2 * 64 + 4 * jt);
                acc.x = fmaf(xv, w.x, acc.x);
                acc.y = fmaf(xv, w.y, acc.y);
                acc.z = fmaf(xv, w.z, acc.z);
                acc.w = fmaf(xv, w.w, acc.w);
            }
            acc.x = fmaxf(acc.x, 0.f); acc.y = fmaxf(acc.y, 0.f);
            acc.z = fmaxf(acc.z, 0.f); acc.w = fmaxf(acc.w, 0.f);
            *(float4*)(sh + g * SH_STRIDE + 4 * jt) = acc;
        }
        __syncthreads();
        // phase 2: Q/K/V = h@{Wq,Wk,Wv}+b, 12 outputs per thread
        {
            float4 aq = *(float4*)(sb + 64 + 4 * jt);
            float4 ak = *(float4*)(sb + 128 + 4 * jt);
            float4 av = *(float4*)(sb + 192 + 4 * jt);
            const float* hr = sh + g * SH_STRIDE;
            #pragma unroll 4
            for (int k2 = 0; k2 < 64; k2++) {
                float hv = hr[k2];
                const float* wr = sW3 + k2 * 192;
                float4 wq = *(float4*)(wr + 4 * jt);
                float4 wk = *(float4*)(wr + 64 + 4 * jt);
                float4 wv = *(float4*)(wr + 128 + 4 * jt);
                aq.x = fmaf(hv, wq.x, aq.x); aq.y = fmaf(hv, wq.y, aq.y);
                aq.z = fmaf(hv, wq.z, aq.z); aq.w = fmaf(hv, wq.w, aq.w);
                ak.x = fmaf(hv, wk.x, ak.x); ak.y = fmaf(hv, wk.y, ak.y);
                ak.z = fmaf(hv, wk.z, ak.z); ak.w = fmaf(hv, wk.w, ak.w);
                av.x = fmaf(hv, wv.x, av.x); av.y = fmaf(hv, wv.y, av.y);
                av.z = fmaf(hv, wv.z, av.z); av.w = fmaf(hv, wv.w, av.w);
            }
            int n = nb + g;
            if (n < Nn) {
                int c = 4 * jt;
                int hidx = c >> 4, d = c & 15;
                size_t base = (size_t)hidx * Nn * 16 + (size_t)n * 16 + d;
                float4 qo, ko;
                qo.x = (aq.x > 0.f) ? (1.f + aq.x) : __expf(aq.x);
                qo.y = (aq.y > 0.f) ? (1.f + aq.y) : __expf(aq.y);
                qo.z = (aq.z > 0.f) ? (1.f + aq.z) : __expf(aq.z);
                qo.w = (aq.w > 0.f) ? (1.f + aq.w) : __expf(aq.w);
                ko.x = (ak.x > 0.f) ? (1.f + ak.x) : __expf(ak.x);
                ko.y = (ak.y > 0.f) ? (1.f + ak.y) : __expf(ak.y);
                ko.z = (ak.z > 0.f) ? (1.f + ak.z) : __expf(ak.z);
                ko.w = (ak.w > 0.f) ? (1.f + ak.w) : __expf(ak.w);
                *(float4*)(g_Q + base)  = qo;
                *(float4*)(g_K0 + base) = ko;
                *(float4*)(g_V + base)  = av;
            }
        }
        __syncthreads();
    }
}

// ---------------- hop epilogue (head-major inputs, fp16 M store) ----------------
__device__ __forceinline__ void hop_epilogue(
    int n, int h, int lane, int d, int ch,
    const float m[8], float kt, int hop, bool first, bool writeM,
    __half* __restrict__ Mout_h, float* __restrict__ Kout_h)
{
    float q = __ldg(g_Q + (size_t)h * Nn * 16 + n * 16 + d);
    float den = q * kt;
    #pragma unroll
    for (int msk = 2; msk <= 16; msk <<= 1) den += __shfl_xor_sync(FULLMASK, den, msk);
    den += 1e-5f;

    float hm[8];
    #pragma unroll
    for (int jj = 0; jj < 8; jj++) {
        float t = q * m[jj];
        #pragma unroll
        for (int msk = 2; msk <= 16; msk <<= 1) t += __shfl_xor_sync(FULLMASK, t, msk);
        hm[jj] = t;
    }

    if (writeM) {
        __half2 p0 = __floats2half2_rn(m[0], m[1]);
        __half2 p1 = __floats2half2_rn(m[2], m[3]);
        __half2 p2 = __floats2half2_rn(m[4], m[5]);
        __half2 p3 = __floats2half2_rn(m[6], m[7]);
        uint4 pk;
        pk.x = *(unsigned*)&p0; pk.y = *(unsigned*)&p1;
        pk.z = *(unsigned*)&p2; pk.w = *(unsigned*)&p3;
        *(uint4*)(Mout_h + (size_t)n * 256 + lane * 8) = pk;
        if (ch == 0) Kout_h[n * 16 + d] = kt;
    }

    if (d == 0) {
        float inv = g_gamma[h * 4 + hop] / den;
        float* hp = g_hid + n * 64 + h * 16 + ch * 8;
        if (first) {
            float t0 = g_temp0[h];
            const float* vp = g_V + (size_t)h * Nn * 16 + n * 16 + ch * 8;
            #pragma unroll
            for (int jj = 0; jj < 8; jj++) hp[jj] = vp[jj] * t0 + hm[jj] * inv;
        } else {
            #pragma unroll
            for (int jj = 0; jj < 8; jj++) hp[jj] += hm[jj] * inv;
        }
    }
}

// ---------------- hop 1: form M0 = Kt0 (x) V on the fly ----------------
__global__ __launch_bounds__(256) void k_hop1() {
    int w = (blockIdx.x * 256 + threadIdx.x) >> 5;
    int lane = threadIdx.x & 31;
    if (w >= Nn * Hh) return;
    int h = w / Nn, n = w - h * Nn;
    int d = lane >> 1, ch = lane & 1;
    const float* __restrict__ K0h = g_K0 + (size_t)h * Nn * 16;
    const float* __restrict__ Vh  = g_V  + (size_t)h * Nn * 16;

    float m[8] = {0, 0, 0, 0, 0, 0, 0, 0};
    float kt = 0.f;
    int beg = g_rowstart[n];
    int deg = g_rowstart[n + 1] - beg;
    for (int base = 0; base < deg; base += 32) {
        int idx = base + lane;
        int s_l = (idx < deg) ? g_csr[beg + idx] : 0;
        int cnt = min(32, deg - base);
        #pragma unroll 4
        for (int i = 0; i < cnt; i++) {
            int s = __shfl_sync(FULLMASK, s_l, i);
            float ks = __ldg(K0h + s * 16 + d);
            const float4* vb = (const float4*)(Vh + s * 16 + ch * 8);
            float4 va = __ldg(vb), vc = __ldg(vb + 1);
            kt += ks;
            m[0] = fmaf(ks, va.x, m[0]); m[1] = fmaf(ks, va.y, m[1]);
            m[2] = fmaf(ks, va.z, m[2]); m[3] = fmaf(ks, va.w, m[3]);
            m[4] = fmaf(ks, vc.x, m[4]); m[5] = fmaf(ks, vc.y, m[5]);
            m[6] = fmaf(ks, vc.z, m[6]); m[7] = fmaf(ks, vc.w, m[7]);
        }
    }
    hop_epilogue(n, h, lane, d, ch, m, kt, 1, true, true,
                 g_Ma + (size_t)h * Nn * 256, g_Ka + (size_t)h * Nn * 16);
}

// ---------------- hops 2,3: gather fp16 M, accumulate in half2 ----------------
__global__ __launch_bounds__(256) void k_hop23(int hop) {
    int w = (blockIdx.x * 256 + threadIdx.x) >> 5;
    int lane = threadIdx.x & 31;
    if (w >= Nn * Hh) return;
    int h = w / Nn, n = w - h * Nn;
    int d = lane >> 1, ch = lane & 1;

    const __half* __restrict__ Min_h = ((hop == 2) ? g_Ma : g_Mb) + (size_t)h * Nn * 256;
    const float*  __restrict__ Kin_h = ((hop == 2) ? g_Ka : g_Kb) + (size_t)h * Nn * 16;
    bool writeM = (hop == 2);

    __half2 acc0 = __float2half2_rn(0.f);
    __half2 acc1 = acc0, acc2 = acc0, acc3 = acc0;
    float kt = 0.f;
    int beg = g_rowstart[n];
    int deg = g_rowstart[n + 1] - beg;
    int lo8 = lane * 8;
    for (int base = 0; base < deg; base += 32) {
        int idx = base + lane;
        int s_l = (idx < deg) ? g_csr[beg + idx] : 0;
        int cnt = min(32, deg - base);
        #pragma unroll 4
        for (int i = 0; i < cnt; i++) {
            int s = __shfl_sync(FULLMASK, s_l, i);
            uint4 pk = __ldg((const uint4*)(Min_h + (size_t)s * 256 + lo8));
            acc0 = __hadd2(acc0, *(__half2*)&pk.x);
            acc1 = __hadd2(acc1, *(__half2*)&pk.y);
            acc2 = __hadd2(acc2, *(__half2*)&pk.z);
            acc3 = __hadd2(acc3, *(__half2*)&pk.w);
            kt += __ldg(Kin_h + s * 16 + d);
        }
    }
    float2 f0 = __half22float2(acc0), f1 = __half22float2(acc1);
    float2 f2 = __half22float2(acc2), f3 = __half22float2(acc3);
    float m[8] = {f0.x, f0.y, f1.x, f1.y, f2.x, f2.y, f3.x, f3.y};
    hop_epilogue(n, h, lane, d, ch, m, kt, hop, false, writeM,
                 g_Mb + (size_t)h * Nn * 256, g_Kb + (size_t)h * Nn * 16);
}

// ---------------- output projection ----------------
__global__ __launch_bounds__(256) void k_out(const float* __restrict__ Wo,
                                             const float* __restrict__ bo,
                                             float* __restrict__ out)
{
    int t = blockIdx.x * blockDim.x + threadIdx.x;
    int n = t >> 4, c = t & 15;
    if (n >= Nn) return;
    float acc = __ldg(bo + c);
    const float* hr = g_hid + n * 64;
    #pragma unroll
    for (int k = 0; k < 64; k++)
        acc = fmaf(hr[k], __ldg(Wo + k * 16 + c), acc);
    out[n * 16 + c] = acc;
}

// ---------------- launcher ----------------
extern "C" void kernel_launch(void* const* d_in, const int* in_sizes, int n_in,
                              void* d_out, int out_size)
{
    const float* x       = (const float*)d_in[0];
    const void*  ei      = d_in[1];
    const float* Wi      = (const float*)d_in[2];
    const float* bi      = (const float*)d_in[3];
    const float* Wq      = (const float*)d_in[4];
    const float* bq      = (const float*)d_in[5];
    const float* Wk      = (const float*)d_in[6];
    const float* bk      = (const float*)d_in[7];
    const float* Wv      = (const float*)d_in[8];
    const float* bv      = (const float*)d_in[9];
    const float* Wo      = (const float*)d_in[10];
    const float* bo      = (const float*)d_in[11];
    const float* hopwise = (const float*)d_in[12];
    const float* temp    = (const float*)d_in[13];
    float* out = (float*)d_out;

    const int qkv_smem = QKV_SMEM_FLOATS * 4;   // ~95.7 KB (R14 container-proven)
    cudaFuncSetAttribute(k_qkv, cudaFuncAttributeMaxDynamicSharedMemorySize, qkv_smem);

    k_init<<<NB + 1, 256>>>((const int*)ei);
    k_edges<<<(Ee + 255) / 256, 256>>>(ei);
    k_scanA<<<NB, 256>>>();
    k_scanC<<<NB, 256>>>();
    k_scatter<<<(Ee + 255) / 256, 256>>>();
    k_sortrows<<<(Nn * 32 + 255) / 256, 256>>>();
    k_gamma<<<1, 32>>>(hopwise, temp);
    k_qkv<<<NB, 256, qkv_smem>>>(x, Wi, bi, Wq, bq, Wk, bk, Wv, bv);

    int hop_blocks = (Nn * Hh + 7) / 8;  // 8 warps/block, 1 warp per (head,node)
    k_hop1<<<hop_blocks, 256>>>();
    k_hop23<<<hop_blocks, 256>>>(2);
    k_hop23<<<hop_blocks, 256>>>(3);

    k_out<<<(Nn * 16 + 255) / 256, 256>>>(Wo, bo, out);
}